// round 11
// baseline (speedup 1.0000x reference)
#include <cuda_runtime.h>

// Row-wise cosine similarity * 0.5 over [B=16384, D=4096] fp32.
// v7 = v1 (best: 76.3us, DRAM 88.1%) with exactly ONE change: __ldcs
// (evict-first streaming) on the 8 batched loads. Data has zero reuse;
// this is the only cache-policy A/B not yet tested unconfounded.
// Structure, launch config, reduction identical to v1.

#define D_DIM 4096
#define THREADS 256

__global__ __launch_bounds__(THREADS) void cosine_rows_v7_kernel(
    const float* __restrict__ x1,
    const float* __restrict__ x2,
    float* __restrict__ out)
{
    const int row = blockIdx.x;
    const int tid = threadIdx.x;

    const float4* r1 = reinterpret_cast<const float4*>(x1 + (size_t)row * D_DIM);
    const float4* r2 = reinterpret_cast<const float4*>(x2 + (size_t)row * D_DIM);

    float dot = 0.f, sx = 0.f, sy = 0.f;

    // 4 float4 per input per thread, front-batched for MLP (as v1)
    float4 a[4], b[4];
#pragma unroll
    for (int i = 0; i < 4; ++i) {
        a[i] = __ldcs(&r1[tid + i * THREADS]);
        b[i] = __ldcs(&r2[tid + i * THREADS]);
    }
#pragma unroll
    for (int i = 0; i < 4; ++i) {
        dot = fmaf(a[i].x, b[i].x, dot);
        dot = fmaf(a[i].y, b[i].y, dot);
        dot = fmaf(a[i].z, b[i].z, dot);
        dot = fmaf(a[i].w, b[i].w, dot);
        sx  = fmaf(a[i].x, a[i].x, sx);
        sx  = fmaf(a[i].y, a[i].y, sx);
        sx  = fmaf(a[i].z, a[i].z, sx);
        sx  = fmaf(a[i].w, a[i].w, sx);
        sy  = fmaf(b[i].x, b[i].x, sy);
        sy  = fmaf(b[i].y, b[i].y, sy);
        sy  = fmaf(b[i].z, b[i].z, sy);
        sy  = fmaf(b[i].w, b[i].w, sy);
    }

    // Warp reduce (3 values)
#pragma unroll
    for (int off = 16; off > 0; off >>= 1) {
        dot += __shfl_down_sync(0xFFFFFFFFu, dot, off);
        sx  += __shfl_down_sync(0xFFFFFFFFu, sx,  off);
        sy  += __shfl_down_sync(0xFFFFFFFFu, sy,  off);
    }

    __shared__ float s_dot[8], s_sx[8], s_sy[8];
    const int wid = tid >> 5;
    const int lid = tid & 31;
    if (lid == 0) { s_dot[wid] = dot; s_sx[wid] = sx; s_sy[wid] = sy; }
    __syncthreads();

    if (wid == 0) {
        dot = (lid < 8) ? s_dot[lid] : 0.f;
        sx  = (lid < 8) ? s_sx[lid]  : 0.f;
        sy  = (lid < 8) ? s_sy[lid]  : 0.f;
#pragma unroll
        for (int off = 4; off > 0; off >>= 1) {
            dot += __shfl_down_sync(0xFFFFFFFFu, dot, off);
            sx  += __shfl_down_sync(0xFFFFFFFFu, sx,  off);
            sy  += __shfl_down_sync(0xFFFFFFFFu, sy,  off);
        }
        if (lid == 0) {
            out[row] = 0.5f * dot * rsqrtf(sx * sy);
        }
    }
}

extern "C" void kernel_launch(void* const* d_in, const int* in_sizes, int n_in,
                              void* d_out, int out_size)
{
    const float* x1 = (const float*)d_in[0];
    const float* x2 = (const float*)d_in[1];
    float* out = (float*)d_out;
    const int B = out_size;  // 16384 rows
    cosine_rows_v7_kernel<<<B, THREADS>>>(x1, x2, out);
}

// round 12
// speedup vs baseline: 1.0267x; 1.0267x over previous
#include <cuda_runtime.h>

// Row-wise cosine similarity * 0.5 over [B=16384, D=4096] fp32.
// FINAL (= v1, best of 7 controlled variants at 76.3us, DRAM 88.1%,
// 6982 GB/s). Pure HBM-bound streaming reduction; 512 MiB read.
// One CTA per row, 256 threads, one front-batched 8-deep float4 load
// burst per thread, warp shuffle + smem cross-warp reduce.
// Falsified alternatives: warp/row (80.7), 2-row pipeline (84.8),
// deeper MLP (78.2), 8-row loop (82.5), fused 512-thr pair (78.0),
// __ldcs (79.9). 88% of HBM spec == LTS-cap roofline on sm_103a.

#define D_DIM 4096
#define THREADS 256

__global__ __launch_bounds__(THREADS) void cosine_rows_kernel(
    const float* __restrict__ x1,
    const float* __restrict__ x2,
    float* __restrict__ out)
{
    const int row = blockIdx.x;
    const int tid = threadIdx.x;

    const float4* r1 = reinterpret_cast<const float4*>(x1 + (size_t)row * D_DIM);
    const float4* r2 = reinterpret_cast<const float4*>(x2 + (size_t)row * D_DIM);

    float dot = 0.f, sx = 0.f, sy = 0.f;

    // 4 float4 per input per thread, front-batched for MLP
    float4 a[4], b[4];
#pragma unroll
    for (int i = 0; i < 4; ++i) {
        a[i] = r1[tid + i * THREADS];
        b[i] = r2[tid + i * THREADS];
    }
#pragma unroll
    for (int i = 0; i < 4; ++i) {
        dot = fmaf(a[i].x, b[i].x, dot);
        dot = fmaf(a[i].y, b[i].y, dot);
        dot = fmaf(a[i].z, b[i].z, dot);
        dot = fmaf(a[i].w, b[i].w, dot);
        sx  = fmaf(a[i].x, a[i].x, sx);
        sx  = fmaf(a[i].y, a[i].y, sx);
        sx  = fmaf(a[i].z, a[i].z, sx);
        sx  = fmaf(a[i].w, a[i].w, sx);
        sy  = fmaf(b[i].x, b[i].x, sy);
        sy  = fmaf(b[i].y, b[i].y, sy);
        sy  = fmaf(b[i].z, b[i].z, sy);
        sy  = fmaf(b[i].w, b[i].w, sy);
    }

    // Warp reduce (3 values)
#pragma unroll
    for (int off = 16; off > 0; off >>= 1) {
        dot += __shfl_down_sync(0xFFFFFFFFu, dot, off);
        sx  += __shfl_down_sync(0xFFFFFFFFu, sx,  off);
        sy  += __shfl_down_sync(0xFFFFFFFFu, sy,  off);
    }

    __shared__ float s_dot[8], s_sx[8], s_sy[8];
    const int wid = tid >> 5;
    const int lid = tid & 31;
    if (lid == 0) { s_dot[wid] = dot; s_sx[wid] = sx; s_sy[wid] = sy; }
    __syncthreads();

    if (wid == 0) {
        dot = (lid < 8) ? s_dot[lid] : 0.f;
        sx  = (lid < 8) ? s_sx[lid]  : 0.f;
        sy  = (lid < 8) ? s_sy[lid]  : 0.f;
#pragma unroll
        for (int off = 4; off > 0; off >>= 1) {
            dot += __shfl_down_sync(0xFFFFFFFFu, dot, off);
            sx  += __shfl_down_sync(0xFFFFFFFFu, sx,  off);
            sy  += __shfl_down_sync(0xFFFFFFFFu, sy,  off);
        }
        if (lid == 0) {
            out[row] = 0.5f * dot * rsqrtf(sx * sy);
        }
    }
}

extern "C" void kernel_launch(void* const* d_in, const int* in_sizes, int n_in,
                              void* d_out, int out_size)
{
    const float* x1 = (const float*)d_in[0];
    const float* x2 = (const float*)d_in[1];
    float* out = (float*)d_out;
    const int B = out_size;  // 16384 rows
    cosine_rows_kernel<<<B, THREADS>>>(x1, x2, out);
}